// round 14
// baseline (speedup 1.0000x reference)
#include <cuda_runtime.h>
#include <math.h>
#include <stdint.h>

// Problem constants
#define TT 64
#define BB 32
#define NN 64
#define DD 128
#define HH 128

// Padded smem strides (floats)
#define SX 132   // 128-wide arrays (x, h, rh, u, q)
#define SC 260   // 256-wide (conv)
#define SS 68    // 64-wide (supports, scores)
#define SK 129   // k-vectors (conflict-free phase-6 reads)

#define CLS 4           // cluster size (CTAs per batch)
#define RP  16          // node rows per CTA
#define NTH 512

// Layer-0 hidden sequence scratch: (T, B, N*H) fp32 = 64 MB
__device__ float g_hs0[(size_t)TT * BB * NN * HH];

__device__ __forceinline__ float fsig(float x) { return 1.0f / (1.0f + __expf(-x)); }
__device__ __forceinline__ float ftanh_(float x) { return 1.0f - 2.0f / (__expf(2.0f * x) + 1.0f); }

__device__ __forceinline__ uint32_t smem_u32p(const void* p) {
    uint32_t a;
    asm("{ .reg .u64 t; cvta.to.shared.u64 t, %1; cvt.u32.u64 %0, t; }" : "=r"(a) : "l"(p));
    return a;
}
__device__ __forceinline__ uint32_t mapa_u32(uint32_t a, int r) {
    uint32_t d;
    asm("mapa.shared::cluster.u32 %0, %1, %2;" : "=r"(d) : "r"(a), "r"(r));
    return d;
}
__device__ __forceinline__ void st_cl_v2(uint32_t a, float x, float y) {
    asm volatile("st.shared::cluster.v2.f32 [%0], {%1, %2};" :: "r"(a), "f"(x), "f"(y) : "memory");
}
__device__ __forceinline__ void st_cl_f32(uint32_t a, float x) {
    asm volatile("st.shared::cluster.f32 [%0], %1;" :: "r"(a), "f"(x) : "memory");
}
#define CLUSTER_SYNC() do { \
    asm volatile("barrier.cluster.arrive.aligned;" ::: "memory"); \
    asm volatile("barrier.cluster.wait.aligned;" ::: "memory"); } while (0)

// K=128 segment, 4 rows x 2 cols accumulator
__device__ __forceinline__ void seg4(float acc[4][2],
    const float* __restrict__ r0, const float* __restrict__ r1,
    const float* __restrict__ r2, const float* __restrict__ r3,
    const float* __restrict__ W, int ldw)
{
#pragma unroll 4
    for (int k = 0; k < 128; ++k) {
        const float2 w = *(const float2*)(W + (size_t)k * ldw);
        float a;
        a = r0[k]; acc[0][0] = fmaf(a, w.x, acc[0][0]); acc[0][1] = fmaf(a, w.y, acc[0][1]);
        a = r1[k]; acc[1][0] = fmaf(a, w.x, acc[1][0]); acc[1][1] = fmaf(a, w.y, acc[1][1]);
        a = r2[k]; acc[2][0] = fmaf(a, w.x, acc[2][0]); acc[2][1] = fmaf(a, w.y, acc[2][1]);
        a = r3[k]; acc[3][0] = fmaf(a, w.x, acc[3][0]); acc[3][1] = fmaf(a, w.y, acc[3][1]);
    }
}

// K=128 segment, 2 rows x 2 cols accumulator
__device__ __forceinline__ void seg2(float acc[2][2],
    const float* __restrict__ r0, const float* __restrict__ r1,
    const float* __restrict__ W, int ldw)
{
#pragma unroll 4
    for (int k = 0; k < 128; ++k) {
        const float2 w = *(const float2*)(W + (size_t)k * ldw);
        float a;
        a = r0[k]; acc[0][0] = fmaf(a, w.x, acc[0][0]); acc[0][1] = fmaf(a, w.y, acc[0][1]);
        a = r1[k]; acc[1][0] = fmaf(a, w.x, acc[1][0]); acc[1][1] = fmaf(a, w.y, acc[1][1]);
    }
}

// conv rows [R0, R0+16) x 256 cols: conv[n,:] = sum_m sup_local[n,m] * [srcx | srch][m,:]
// 256 threads: 4 row-groups (4 rows) x 64 float4-col-groups
__device__ __forceinline__ void conv_phase(int tid,
    const float* __restrict__ srcx, const float* __restrict__ srch,
    const float* __restrict__ s_sup, float* __restrict__ s_conv)
{
    const int rowg = tid >> 6;          // 0..3
    const int nl0  = rowg << 2;         // local rows nl0..nl0+3
    const int c4   = (tid & 63) << 2;   // 0..252
    const float* src = (c4 < 128) ? (srcx + c4) : (srch + (c4 - 128));
    const float* sup = s_sup + nl0 * SS;
    float4 a0 = make_float4(0.f,0.f,0.f,0.f), a1 = a0, a2 = a0, a3 = a0;
#pragma unroll 4
    for (int m = 0; m < NN; ++m) {
        const float4 v = *(const float4*)(src + m * SX);
        const float sA = sup[m], sB = sup[SS + m], sC = sup[2*SS + m], sD = sup[3*SS + m];
        a0.x = fmaf(sA, v.x, a0.x); a0.y = fmaf(sA, v.y, a0.y); a0.z = fmaf(sA, v.z, a0.z); a0.w = fmaf(sA, v.w, a0.w);
        a1.x = fmaf(sB, v.x, a1.x); a1.y = fmaf(sB, v.y, a1.y); a1.z = fmaf(sB, v.z, a1.z); a1.w = fmaf(sB, v.w, a1.w);
        a2.x = fmaf(sC, v.x, a2.x); a2.y = fmaf(sC, v.y, a2.y); a2.z = fmaf(sC, v.z, a2.z); a2.w = fmaf(sC, v.w, a2.w);
        a3.x = fmaf(sD, v.x, a3.x); a3.y = fmaf(sD, v.y, a3.y); a3.z = fmaf(sD, v.z, a3.z); a3.w = fmaf(sD, v.w, a3.w);
    }
    *(float4*)(s_conv + (nl0+0) * SC + c4) = a0;
    *(float4*)(s_conv + (nl0+1) * SC + c4) = a1;
    *(float4*)(s_conv + (nl0+2) * SC + c4) = a2;
    *(float4*)(s_conv + (nl0+3) * SC + c4) = a3;
}

// smem floats: 3*64*SX + 64*SK + 2*16*SX + 16*SC + 16*SS
#define SMEM_FLOATS (3*64*SX + 64*SK + 2*16*SX + 16*SC + 16*SS)
#define SMEM_BYTES  (SMEM_FLOATS * (int)sizeof(float))

__global__ void __launch_bounds__(NTH, 1) __cluster_dims__(CLS, 1, 1)
sglc_kernel(const float* __restrict__ inputs,
            const float* __restrict__ h0_all,
            const float* __restrict__ sup0,
            const float* __restrict__ Wg0, const float* __restrict__ bg0,
            const float* __restrict__ Wc0, const float* __restrict__ bc0,
            const float* __restrict__ Wq0, const float* __restrict__ Wk0,
            const float* __restrict__ Wg1, const float* __restrict__ bg1,
            const float* __restrict__ Wc1, const float* __restrict__ bc1,
            const float* __restrict__ Wq1, const float* __restrict__ Wk1,
            float* __restrict__ out)
{
    extern __shared__ float sm[];
    float* s_x    = sm;                    // 64 x SX (full)
    float* s_h    = s_x  + 64 * SX;        // 64 x SX (full, replicated)
    float* s_rh   = s_h  + 64 * SX;        // 64 x SX (full, replicated)
    float* s_k    = s_rh + 64 * SX;        // 64 x SK (full, replicated)
    float* s_q    = s_k  + 64 * SK;        // 16 x SX (local quarter)
    float* s_u    = s_q  + 16 * SX;        // 16 x SX (local quarter)
    float* s_conv = s_u  + 16 * SX;        // 16 x SC (local quarter)
    float* s_sup  = s_conv + 16 * SC;      // 16 x SS (local quarter)
    float* s_sc   = s_u;                   // scores alias (16 x SS fits)

    const int tid   = threadIdx.x;
    const int batch = blockIdx.x >> 2;
    const int rank  = blockIdx.x & 3;
    const int R0    = rank * RP;

    // Peer smem base addresses (all 4 ranks) for push-broadcast buffers
    const uint32_t rh_u = smem_u32p(s_rh);
    const uint32_t h_u  = smem_u32p(s_h);
    const uint32_t k_u  = smem_u32p(s_k);
    uint32_t rh_p[CLS], h_p[CLS], k_p[CLS];
#pragma unroll
    for (int r = 0; r < CLS; ++r) {
        rh_p[r] = mapa_u32(rh_u, r);
        h_p[r]  = mapa_u32(h_u, r);
        k_p[r]  = mapa_u32(k_u, r);
    }

    // Load local 16 rows of initial supports
    for (int i = tid; i < RP * NN; i += NTH) {
        const int lr = i >> 6, c = i & 63;
        s_sup[lr * SS + c] = sup0[(size_t)batch * NN * NN + (R0 + lr) * NN + c];
    }

    for (int layer = 0; layer < 2; ++layer) {
        const float* Wg = layer ? Wg1 : Wg0;
        const float* bg = layer ? bg1 : bg0;
        const float* Wc = layer ? Wc1 : Wc0;
        const float* bc = layer ? bc1 : bc0;
        const float* Wq = layer ? Wq1 : Wq0;
        const float* Wk = layer ? Wk1 : Wk0;

        // Full initial hidden state (each CTA holds a replica)
        for (int i = tid; i < NN * HH; i += NTH)
            s_h[(i >> 7) * SX + (i & 127)] = h0_all[((size_t)layer * BB + batch) * NN * HH + i];
        __syncthreads();

        for (int t = 0; t < TT; ++t) {
            // ---------- P0: load full x_t ----------
            const float* xsrc = (layer == 0)
                ? inputs + (size_t)(t * BB + batch) * NN * DD
                : g_hs0  + (size_t)(t * BB + batch) * NN * HH;
            for (int i = tid; i < NN * 32; i += NTH) {
                const int row = i >> 5, c4 = (i & 31) << 2;
                *(float4*)(s_x + row * SX + c4) = *(const float4*)(xsrc + row * 128 + c4);
            }
            __syncthreads();

            // ---------- P1: conv = sup_local @ [x|h] (16 rows) ----------
            if (tid < 256) conv_phase(tid, s_x, s_h, s_sup, s_conv);
            __syncthreads();

            // ---------- P2: gates (16 rows x 256 cols, K=512) ----------
            {
                const int rowg = tid >> 7;          // 0..3
                const int nl0  = rowg << 2;
                const int j0   = (tid & 127) << 1;  // 0..254
                const int gn0  = R0 + nl0;
                float acc[4][2];
                const float b0v = bg[j0], b1v = bg[j0 + 1];
#pragma unroll
                for (int i = 0; i < 4; ++i) { acc[i][0] = b0v; acc[i][1] = b1v; }
                seg4(acc, s_x + (gn0+0)*SX, s_x + (gn0+1)*SX, s_x + (gn0+2)*SX, s_x + (gn0+3)*SX,
                     Wg + j0, 256);
                seg4(acc, s_h + (gn0+0)*SX, s_h + (gn0+1)*SX, s_h + (gn0+2)*SX, s_h + (gn0+3)*SX,
                     Wg + 128*256 + j0, 256);
                seg4(acc, s_conv + (nl0+0)*SC, s_conv + (nl0+1)*SC, s_conv + (nl0+2)*SC, s_conv + (nl0+3)*SC,
                     Wg + 256*256 + j0, 256);
                seg4(acc, s_conv + (nl0+0)*SC + 128, s_conv + (nl0+1)*SC + 128,
                     s_conv + (nl0+2)*SC + 128, s_conv + (nl0+3)*SC + 128,
                     Wg + 384*256 + j0, 256);
                if (j0 < 128) {
#pragma unroll
                    for (int i = 0; i < 4; ++i) {
                        const int gn = gn0 + i;
                        const float rv0 = fsig(acc[i][0]) * s_h[gn*SX + j0];
                        const float rv1 = fsig(acc[i][1]) * s_h[gn*SX + j0 + 1];
                        s_rh[gn*SX + j0]     = rv0;
                        s_rh[gn*SX + j0 + 1] = rv1;
                        const uint32_t off = (uint32_t)(gn * SX + j0) * 4u;
#pragma unroll
                        for (int rr = 0; rr < CLS; ++rr)
                            if (rr != rank) st_cl_v2(rh_p[rr] + off, rv0, rv1);
                    }
                } else {
                    const int ju = j0 - 128;
#pragma unroll
                    for (int i = 0; i < 4; ++i) {
                        s_u[(nl0+i)*SX + ju]     = fsig(acc[i][0]);
                        s_u[(nl0+i)*SX + ju + 1] = fsig(acc[i][1]);
                    }
                }
            }
            CLUSTER_SYNC();   // B1: rh replicas complete everywhere

            // ---------- P3: conv_c = sup_local @ [x|rh] ----------
            if (tid < 256) conv_phase(tid, s_x, s_rh, s_sup, s_conv);
            __syncthreads();

            // ---------- P4: c = tanh(...), h = u*h + (1-u)*c ----------
            float* hdst = (layer == 0)
                ? g_hs0 + (size_t)(t * BB + batch) * NN * HH
                : out + (size_t)2 * BB * NN * HH + (size_t)(t * BB + batch) * NN * HH;
            {
                const int rowg = tid >> 6;          // 0..7
                const int nl0  = rowg << 1;
                const int j0   = (tid & 63) << 1;   // 0..126
                const int gn0  = R0 + nl0;
                float acc[2][2];
                const float b0v = bc[j0], b1v = bc[j0 + 1];
                acc[0][0] = b0v; acc[0][1] = b1v; acc[1][0] = b0v; acc[1][1] = b1v;
                seg2(acc, s_x  + (gn0+0)*SX, s_x  + (gn0+1)*SX, Wc + j0, 128);
                seg2(acc, s_rh + (gn0+0)*SX, s_rh + (gn0+1)*SX, Wc + 128*128 + j0, 128);
                seg2(acc, s_conv + (nl0+0)*SC, s_conv + (nl0+1)*SC, Wc + 256*128 + j0, 128);
                seg2(acc, s_conv + (nl0+0)*SC + 128, s_conv + (nl0+1)*SC + 128, Wc + 384*128 + j0, 128);
#pragma unroll
                for (int i = 0; i < 2; ++i) {
                    const int gn = gn0 + i, nl = nl0 + i;
                    const float c0 = ftanh_(acc[i][0]);
                    const float c1 = ftanh_(acc[i][1]);
                    const float u0 = s_u[nl*SX + j0], u1 = s_u[nl*SX + j0 + 1];
                    const float hn0 = u0 * s_h[gn*SX + j0]     + (1.0f - u0) * c0;
                    const float hn1 = u1 * s_h[gn*SX + j0 + 1] + (1.0f - u1) * c1;
                    s_h[gn*SX + j0]     = hn0;
                    s_h[gn*SX + j0 + 1] = hn1;
                    const uint32_t off = (uint32_t)(gn * SX + j0) * 4u;
#pragma unroll
                    for (int rr = 0; rr < CLS; ++rr)
                        if (rr != rank) st_cl_v2(h_p[rr] + off, hn0, hn1);
                    *(float2*)(hdst + gn * HH + j0) = make_float2(hn0, hn1);
                }
            }
            __syncthreads();

            // ---------- P5: q (local) | k (replicated) = h_new @ [Wq|Wk] ----------
            {
                const int rowg = tid >> 7;
                const int nl0  = rowg << 2;
                const int j0   = (tid & 127) << 1;
                const int gn0  = R0 + nl0;
                float acc[4][2];
#pragma unroll
                for (int i = 0; i < 4; ++i) { acc[i][0] = 0.f; acc[i][1] = 0.f; }
                const float* Wb = (j0 < 128) ? (Wq + j0) : (Wk + (j0 - 128));
                seg4(acc, s_h + (gn0+0)*SX, s_h + (gn0+1)*SX, s_h + (gn0+2)*SX, s_h + (gn0+3)*SX,
                     Wb, 128);
                if (j0 < 128) {
#pragma unroll
                    for (int i = 0; i < 4; ++i) {
                        s_q[(nl0+i)*SX + j0]     = acc[i][0];
                        s_q[(nl0+i)*SX + j0 + 1] = acc[i][1];
                    }
                } else {
                    const int jk = j0 - 128;
#pragma unroll
                    for (int i = 0; i < 4; ++i) {
                        const int gn = gn0 + i;
                        s_k[gn*SK + jk]     = acc[i][0];
                        s_k[gn*SK + jk + 1] = acc[i][1];
                        const uint32_t off = (uint32_t)(gn * SK + jk) * 4u;
#pragma unroll
                        for (int rr = 0; rr < CLS; ++rr)
                            if (rr != rank) {
                                st_cl_f32(k_p[rr] + off,     acc[i][0]);
                                st_cl_f32(k_p[rr] + off + 4, acc[i][1]);
                            }
                    }
                }
            }
            CLUSTER_SYNC();   // B2: h and k replicas complete everywhere

            // ---------- P6: scores = relu(q_local @ k_full^T) (16 x 64) ----------
            if (tid < 128) {
                const int rowg = tid >> 5;      // 0..3
                const int nl0  = rowg << 2;     // 4 local rows
                const int lane = tid & 31;
                const int m0   = lane << 1;
                float acc[4][2];
#pragma unroll
                for (int i = 0; i < 4; ++i) { acc[i][0] = 0.f; acc[i][1] = 0.f; }
                const float* qr = s_q + nl0 * SX;
                const float* k0p = s_k + m0 * SK;
                const float* k1p = k0p + SK;
#pragma unroll 4
                for (int d = 0; d < 128; ++d) {
                    const float kv0 = k0p[d], kv1 = k1p[d];
                    float qv;
                    qv = qr[d];        acc[0][0] = fmaf(qv, kv0, acc[0][0]); acc[0][1] = fmaf(qv, kv1, acc[0][1]);
                    qv = qr[SX + d];   acc[1][0] = fmaf(qv, kv0, acc[1][0]); acc[1][1] = fmaf(qv, kv1, acc[1][1]);
                    qv = qr[2*SX + d]; acc[2][0] = fmaf(qv, kv0, acc[2][0]); acc[2][1] = fmaf(qv, kv1, acc[2][1]);
                    qv = qr[3*SX + d]; acc[3][0] = fmaf(qv, kv0, acc[3][0]); acc[3][1] = fmaf(qv, kv1, acc[3][1]);
                }
#pragma unroll
                for (int i = 0; i < 4; ++i) {
                    s_sc[(nl0+i)*SS + m0]     = fmaxf(acc[i][0], 0.0f);
                    s_sc[(nl0+i)*SS + m0 + 1] = fmaxf(acc[i][1], 0.0f);
                }
            }
            __syncthreads();

            // ---------- P7: row softmax -> local supports ----------
            {
                const int w    = tid >> 5;   // local row 0..15
                const int lane = tid & 31;
                const float v0 = s_sc[w*SS + lane];
                const float v1 = s_sc[w*SS + 32 + lane];
                float mx = fmaxf(v0, v1);
#pragma unroll
                for (int o = 16; o > 0; o >>= 1) mx = fmaxf(mx, __shfl_xor_sync(0xffffffffu, mx, o));
                const float e0 = __expf(v0 - mx);
                const float e1 = __expf(v1 - mx);
                float s = e0 + e1;
#pragma unroll
                for (int o = 16; o > 0; o >>= 1) s += __shfl_xor_sync(0xffffffffu, s, o);
                const float inv = 1.0f / s;
                s_sup[w*SS + lane]      = e0 * inv;
                s_sup[w*SS + 32 + lane] = e1 * inv;
            }
            __syncthreads();
        }

        // Store h_last quarter into output_hidden
        for (int i = tid; i < RP * HH; i += NTH) {
            const int lr = i >> 7, c = i & 127;
            out[((size_t)layer * BB + batch) * NN * HH + (size_t)(R0 + lr) * HH + c]
                = s_h[(R0 + lr) * SX + c];
        }
        __syncthreads();
    }
}

extern "C" void kernel_launch(void* const* d_in, const int* in_sizes, int n_in,
                              void* d_out, int out_size) {
    (void)in_sizes; (void)n_in; (void)out_size;
    const float* inputs = (const float*)d_in[0];
    const float* h0     = (const float*)d_in[1];
    const float* sup    = (const float*)d_in[2];
    const float* Wg0    = (const float*)d_in[3];
    const float* bg0    = (const float*)d_in[4];
    const float* Wc0    = (const float*)d_in[5];
    const float* bc0    = (const float*)d_in[6];
    const float* Wq0    = (const float*)d_in[7];
    const float* Wk0    = (const float*)d_in[8];
    const float* Wg1    = (const float*)d_in[9];
    const float* bg1    = (const float*)d_in[10];
    const float* Wc1    = (const float*)d_in[11];
    const float* bc1    = (const float*)d_in[12];
    const float* Wq1    = (const float*)d_in[13];
    const float* Wk1    = (const float*)d_in[14];
    float* out          = (float*)d_out;

    static bool attr_set = false;
    if (!attr_set) {
        cudaFuncSetAttribute(sglc_kernel, cudaFuncAttributeMaxDynamicSharedMemorySize, SMEM_BYTES);
        attr_set = true;
    }

    sglc_kernel<<<BB * CLS, NTH, SMEM_BYTES>>>(inputs, h0, sup,
                                               Wg0, bg0, Wc0, bc0, Wq0, Wk0,
                                               Wg1, bg1, Wc1, bc1, Wq1, Wk1,
                                               out);
}

// round 15
// speedup vs baseline: 1.0055x; 1.0055x over previous
#include <cuda_runtime.h>
#include <math.h>
#include <stdint.h>

// Problem constants
#define TT 64
#define BB 32
#define NN 64
#define DD 128
#define HH 128

// Padded smem strides (floats)
#define SX 132   // 128-wide arrays (x, h, rh, u, q)
#define SC 260   // 256-wide (conv)
#define SS 68    // 64-wide (supports, scores)
#define SK 129   // k-vectors (conflict-free phase-6 reads)

#define CLS 4           // cluster size (CTAs per batch)
#define RP  16          // node rows per CTA
#define NTH 512

// Layer-0 hidden sequence scratch: (T, B, N*H) fp32 = 64 MB
__device__ float g_hs0[(size_t)TT * BB * NN * HH];

__device__ __forceinline__ float fsig(float x) { return 1.0f / (1.0f + __expf(-x)); }
__device__ __forceinline__ float ftanh_(float x) { return 1.0f - 2.0f / (__expf(2.0f * x) + 1.0f); }

__device__ __forceinline__ uint32_t smem_u32p(const void* p) {
    uint32_t a;
    asm("{ .reg .u64 t; cvta.to.shared.u64 t, %1; cvt.u32.u64 %0, t; }" : "=r"(a) : "l"(p));
    return a;
}
__device__ __forceinline__ uint32_t mapa_u32(uint32_t a, int r) {
    uint32_t d;
    asm("mapa.shared::cluster.u32 %0, %1, %2;" : "=r"(d) : "r"(a), "r"(r));
    return d;
}
__device__ __forceinline__ void st_cl_v2(uint32_t a, float x, float y) {
    asm volatile("st.shared::cluster.v2.f32 [%0], {%1, %2};" :: "r"(a), "f"(x), "f"(y) : "memory");
}
__device__ __forceinline__ void st_cl_f32(uint32_t a, float x) {
    asm volatile("st.shared::cluster.f32 [%0], %1;" :: "r"(a), "f"(x) : "memory");
}
#define CLUSTER_SYNC() do { \
    asm volatile("barrier.cluster.arrive.aligned;" ::: "memory"); \
    asm volatile("barrier.cluster.wait.aligned;" ::: "memory"); } while (0)

// K=128 segment, 4 rows x 2 cols accumulator
__device__ __forceinline__ void seg4(float acc[4][2],
    const float* __restrict__ r0, const float* __restrict__ r1,
    const float* __restrict__ r2, const float* __restrict__ r3,
    const float* __restrict__ W, int ldw)
{
#pragma unroll 4
    for (int k = 0; k < 128; ++k) {
        const float2 w = *(const float2*)(W + (size_t)k * ldw);
        float a;
        a = r0[k]; acc[0][0] = fmaf(a, w.x, acc[0][0]); acc[0][1] = fmaf(a, w.y, acc[0][1]);
        a = r1[k]; acc[1][0] = fmaf(a, w.x, acc[1][0]); acc[1][1] = fmaf(a, w.y, acc[1][1]);
        a = r2[k]; acc[2][0] = fmaf(a, w.x, acc[2][0]); acc[2][1] = fmaf(a, w.y, acc[2][1]);
        a = r3[k]; acc[3][0] = fmaf(a, w.x, acc[3][0]); acc[3][1] = fmaf(a, w.y, acc[3][1]);
    }
}

// K=128 segment, 2 rows x 2 cols accumulator
__device__ __forceinline__ void seg2(float acc[2][2],
    const float* __restrict__ r0, const float* __restrict__ r1,
    const float* __restrict__ W, int ldw)
{
#pragma unroll 4
    for (int k = 0; k < 128; ++k) {
        const float2 w = *(const float2*)(W + (size_t)k * ldw);
        float a;
        a = r0[k]; acc[0][0] = fmaf(a, w.x, acc[0][0]); acc[0][1] = fmaf(a, w.y, acc[0][1]);
        a = r1[k]; acc[1][0] = fmaf(a, w.x, acc[1][0]); acc[1][1] = fmaf(a, w.y, acc[1][1]);
    }
}

// conv rows [R0, R0+16) x 256 cols: conv[n,:] = sum_m sup_local[n,m] * [srcx | srch][m,:]
// 256 threads: 4 row-groups (4 rows) x 64 float4-col-groups
__device__ __forceinline__ void conv_phase(int tid,
    const float* __restrict__ srcx, const float* __restrict__ srch,
    const float* __restrict__ s_sup, float* __restrict__ s_conv)
{
    const int rowg = tid >> 6;          // 0..3
    const int nl0  = rowg << 2;         // local rows nl0..nl0+3
    const int c4   = (tid & 63) << 2;   // 0..252
    const float* src = (c4 < 128) ? (srcx + c4) : (srch + (c4 - 128));
    const float* sup = s_sup + nl0 * SS;
    float4 a0 = make_float4(0.f,0.f,0.f,0.f), a1 = a0, a2 = a0, a3 = a0;
#pragma unroll 4
    for (int m = 0; m < NN; ++m) {
        const float4 v = *(const float4*)(src + m * SX);
        const float sA = sup[m], sB = sup[SS + m], sC = sup[2*SS + m], sD = sup[3*SS + m];
        a0.x = fmaf(sA, v.x, a0.x); a0.y = fmaf(sA, v.y, a0.y); a0.z = fmaf(sA, v.z, a0.z); a0.w = fmaf(sA, v.w, a0.w);
        a1.x = fmaf(sB, v.x, a1.x); a1.y = fmaf(sB, v.y, a1.y); a1.z = fmaf(sB, v.z, a1.z); a1.w = fmaf(sB, v.w, a1.w);
        a2.x = fmaf(sC, v.x, a2.x); a2.y = fmaf(sC, v.y, a2.y); a2.z = fmaf(sC, v.z, a2.z); a2.w = fmaf(sC, v.w, a2.w);
        a3.x = fmaf(sD, v.x, a3.x); a3.y = fmaf(sD, v.y, a3.y); a3.z = fmaf(sD, v.z, a3.z); a3.w = fmaf(sD, v.w, a3.w);
    }
    *(float4*)(s_conv + (nl0+0) * SC + c4) = a0;
    *(float4*)(s_conv + (nl0+1) * SC + c4) = a1;
    *(float4*)(s_conv + (nl0+2) * SC + c4) = a2;
    *(float4*)(s_conv + (nl0+3) * SC + c4) = a3;
}

// smem floats: 3*64*SX + 64*SK + 2*16*SX + 16*SC + 16*SS
#define SMEM_FLOATS (3*64*SX + 64*SK + 2*16*SX + 16*SC + 16*SS)
#define SMEM_BYTES  (SMEM_FLOATS * (int)sizeof(float))

__global__ void __launch_bounds__(NTH, 1) __cluster_dims__(CLS, 1, 1)
sglc_kernel(const float* __restrict__ inputs,
            const float* __restrict__ h0_all,
            const float* __restrict__ sup0,
            const float* __restrict__ Wg0, const float* __restrict__ bg0,
            const float* __restrict__ Wc0, const float* __restrict__ bc0,
            const float* __restrict__ Wq0, const float* __restrict__ Wk0,
            const float* __restrict__ Wg1, const float* __restrict__ bg1,
            const float* __restrict__ Wc1, const float* __restrict__ bc1,
            const float* __restrict__ Wq1, const float* __restrict__ Wk1,
            float* __restrict__ out)
{
    extern __shared__ float sm[];
    float* s_x    = sm;                    // 64 x SX (full)
    float* s_h    = s_x  + 64 * SX;        // 64 x SX (full, replicated)
    float* s_rh   = s_h  + 64 * SX;        // 64 x SX (full, replicated)
    float* s_k    = s_rh + 64 * SX;        // 64 x SK (full, replicated)
    float* s_q    = s_k  + 64 * SK;        // 16 x SX (local quarter)
    float* s_u    = s_q  + 16 * SX;        // 16 x SX (local quarter)
    float* s_conv = s_u  + 16 * SX;        // 16 x SC (local quarter)
    float* s_sup  = s_conv + 16 * SC;      // 16 x SS (local quarter)
    float* s_sc   = s_u;                   // scores alias (16 x SS fits)

    const int tid   = threadIdx.x;
    const int batch = blockIdx.x >> 2;
    const int rank  = blockIdx.x & 3;
    const int R0    = rank * RP;

    // Peer smem base addresses (all 4 ranks) for push-broadcast buffers
    const uint32_t rh_u = smem_u32p(s_rh);
    const uint32_t h_u  = smem_u32p(s_h);
    const uint32_t k_u  = smem_u32p(s_k);
    uint32_t rh_p[CLS], h_p[CLS], k_p[CLS];
#pragma unroll
    for (int r = 0; r < CLS; ++r) {
        rh_p[r] = mapa_u32(rh_u, r);
        h_p[r]  = mapa_u32(h_u, r);
        k_p[r]  = mapa_u32(k_u, r);
    }

    // Load local 16 rows of initial supports
    for (int i = tid; i < RP * NN; i += NTH) {
        const int lr = i >> 6, c = i & 63;
        s_sup[lr * SS + c] = sup0[(size_t)batch * NN * NN + (R0 + lr) * NN + c];
    }

    for (int layer = 0; layer < 2; ++layer) {
        const float* Wg = layer ? Wg1 : Wg0;
        const float* bg = layer ? bg1 : bg0;
        const float* Wc = layer ? Wc1 : Wc0;
        const float* bc = layer ? bc1 : bc0;
        const float* Wq = layer ? Wq1 : Wq0;
        const float* Wk = layer ? Wk1 : Wk0;

        // Full initial hidden state (each CTA holds a replica)
        for (int i = tid; i < NN * HH; i += NTH)
            s_h[(i >> 7) * SX + (i & 127)] = h0_all[((size_t)layer * BB + batch) * NN * HH + i];
        __syncthreads();

        for (int t = 0; t < TT; ++t) {
            // ---------- P0: load full x_t ----------
            const float* xsrc = (layer == 0)
                ? inputs + (size_t)(t * BB + batch) * NN * DD
                : g_hs0  + (size_t)(t * BB + batch) * NN * HH;
            for (int i = tid; i < NN * 32; i += NTH) {
                const int row = i >> 5, c4 = (i & 31) << 2;
                *(float4*)(s_x + row * SX + c4) = *(const float4*)(xsrc + row * 128 + c4);
            }
            __syncthreads();

            // ---------- P1: conv = sup_local @ [x|h] (16 rows) ----------
            if (tid < 256) conv_phase(tid, s_x, s_h, s_sup, s_conv);
            __syncthreads();

            // ---------- P2: gates (16 rows x 256 cols, K=512) ----------
            {
                const int rowg = tid >> 7;          // 0..3
                const int nl0  = rowg << 2;
                const int j0   = (tid & 127) << 1;  // 0..254
                const int gn0  = R0 + nl0;
                float acc[4][2];
                const float b0v = bg[j0], b1v = bg[j0 + 1];
#pragma unroll
                for (int i = 0; i < 4; ++i) { acc[i][0] = b0v; acc[i][1] = b1v; }
                seg4(acc, s_x + (gn0+0)*SX, s_x + (gn0+1)*SX, s_x + (gn0+2)*SX, s_x + (gn0+3)*SX,
                     Wg + j0, 256);
                seg4(acc, s_h + (gn0+0)*SX, s_h + (gn0+1)*SX, s_h + (gn0+2)*SX, s_h + (gn0+3)*SX,
                     Wg + 128*256 + j0, 256);
                seg4(acc, s_conv + (nl0+0)*SC, s_conv + (nl0+1)*SC, s_conv + (nl0+2)*SC, s_conv + (nl0+3)*SC,
                     Wg + 256*256 + j0, 256);
                seg4(acc, s_conv + (nl0+0)*SC + 128, s_conv + (nl0+1)*SC + 128,
                     s_conv + (nl0+2)*SC + 128, s_conv + (nl0+3)*SC + 128,
                     Wg + 384*256 + j0, 256);
                if (j0 < 128) {
#pragma unroll
                    for (int i = 0; i < 4; ++i) {
                        const int gn = gn0 + i;
                        const float rv0 = fsig(acc[i][0]) * s_h[gn*SX + j0];
                        const float rv1 = fsig(acc[i][1]) * s_h[gn*SX + j0 + 1];
                        s_rh[gn*SX + j0]     = rv0;
                        s_rh[gn*SX + j0 + 1] = rv1;
                        const uint32_t off = (uint32_t)(gn * SX + j0) * 4u;
#pragma unroll
                        for (int rr = 0; rr < CLS; ++rr)
                            if (rr != rank) st_cl_v2(rh_p[rr] + off, rv0, rv1);
                    }
                } else {
                    const int ju = j0 - 128;
#pragma unroll
                    for (int i = 0; i < 4; ++i) {
                        s_u[(nl0+i)*SX + ju]     = fsig(acc[i][0]);
                        s_u[(nl0+i)*SX + ju + 1] = fsig(acc[i][1]);
                    }
                }
            }
            CLUSTER_SYNC();   // B1: rh replicas complete everywhere

            // ---------- P3: conv_c = sup_local @ [x|rh] ----------
            if (tid < 256) conv_phase(tid, s_x, s_rh, s_sup, s_conv);
            __syncthreads();

            // ---------- P4: c = tanh(...), h = u*h + (1-u)*c ----------
            float* hdst = (layer == 0)
                ? g_hs0 + (size_t)(t * BB + batch) * NN * HH
                : out + (size_t)2 * BB * NN * HH + (size_t)(t * BB + batch) * NN * HH;
            {
                const int rowg = tid >> 6;          // 0..7
                const int nl0  = rowg << 1;
                const int j0   = (tid & 63) << 1;   // 0..126
                const int gn0  = R0 + nl0;
                float acc[2][2];
                const float b0v = bc[j0], b1v = bc[j0 + 1];
                acc[0][0] = b0v; acc[0][1] = b1v; acc[1][0] = b0v; acc[1][1] = b1v;
                seg2(acc, s_x  + (gn0+0)*SX, s_x  + (gn0+1)*SX, Wc + j0, 128);
                seg2(acc, s_rh + (gn0+0)*SX, s_rh + (gn0+1)*SX, Wc + 128*128 + j0, 128);
                seg2(acc, s_conv + (nl0+0)*SC, s_conv + (nl0+1)*SC, Wc + 256*128 + j0, 128);
                seg2(acc, s_conv + (nl0+0)*SC + 128, s_conv + (nl0+1)*SC + 128, Wc + 384*128 + j0, 128);
#pragma unroll
                for (int i = 0; i < 2; ++i) {
                    const int gn = gn0 + i, nl = nl0 + i;
                    const float c0 = ftanh_(acc[i][0]);
                    const float c1 = ftanh_(acc[i][1]);
                    const float u0 = s_u[nl*SX + j0], u1 = s_u[nl*SX + j0 + 1];
                    const float hn0 = u0 * s_h[gn*SX + j0]     + (1.0f - u0) * c0;
                    const float hn1 = u1 * s_h[gn*SX + j0 + 1] + (1.0f - u1) * c1;
                    s_h[gn*SX + j0]     = hn0;
                    s_h[gn*SX + j0 + 1] = hn1;
                    const uint32_t off = (uint32_t)(gn * SX + j0) * 4u;
#pragma unroll
                    for (int rr = 0; rr < CLS; ++rr)
                        if (rr != rank) st_cl_v2(h_p[rr] + off, hn0, hn1);
                    *(float2*)(hdst + gn * HH + j0) = make_float2(hn0, hn1);
                }
            }
            __syncthreads();

            // ---------- P5: q (local) | k (replicated) = h_new @ [Wq|Wk] ----------
            {
                const int rowg = tid >> 7;
                const int nl0  = rowg << 2;
                const int j0   = (tid & 127) << 1;
                const int gn0  = R0 + nl0;
                float acc[4][2];
#pragma unroll
                for (int i = 0; i < 4; ++i) { acc[i][0] = 0.f; acc[i][1] = 0.f; }
                const float* Wb = (j0 < 128) ? (Wq + j0) : (Wk + (j0 - 128));
                seg4(acc, s_h + (gn0+0)*SX, s_h + (gn0+1)*SX, s_h + (gn0+2)*SX, s_h + (gn0+3)*SX,
                     Wb, 128);
                if (j0 < 128) {
#pragma unroll
                    for (int i = 0; i < 4; ++i) {
                        s_q[(nl0+i)*SX + j0]     = acc[i][0];
                        s_q[(nl0+i)*SX + j0 + 1] = acc[i][1];
                    }
                } else {
                    const int jk = j0 - 128;
#pragma unroll
                    for (int i = 0; i < 4; ++i) {
                        const int gn = gn0 + i;
                        s_k[gn*SK + jk]     = acc[i][0];
                        s_k[gn*SK + jk + 1] = acc[i][1];
                        const uint32_t off = (uint32_t)(gn * SK + jk) * 4u;
#pragma unroll
                        for (int rr = 0; rr < CLS; ++rr)
                            if (rr != rank) {
                                st_cl_f32(k_p[rr] + off,     acc[i][0]);
                                st_cl_f32(k_p[rr] + off + 4, acc[i][1]);
                            }
                    }
                }
            }
            CLUSTER_SYNC();   // B2: h and k replicas complete everywhere

            // ---------- P6: scores = relu(q_local @ k_full^T) (16 x 64) ----------
            if (tid < 128) {
                const int rowg = tid >> 5;      // 0..3
                const int nl0  = rowg << 2;     // 4 local rows
                const int lane = tid & 31;
                const int m0   = lane << 1;
                float acc[4][2];
#pragma unroll
                for (int i = 0; i < 4; ++i) { acc[i][0] = 0.f; acc[i][1] = 0.f; }
                const float* qr = s_q + nl0 * SX;
                const float* k0p = s_k + m0 * SK;
                const float* k1p = k0p + SK;
#pragma unroll 4
                for (int d = 0; d < 128; ++d) {
                    const float kv0 = k0p[d], kv1 = k1p[d];
                    float qv;
                    qv = qr[d];        acc[0][0] = fmaf(qv, kv0, acc[0][0]); acc[0][1] = fmaf(qv, kv1, acc[0][1]);
                    qv = qr[SX + d];   acc[1][0] = fmaf(qv, kv0, acc[1][0]); acc[1][1] = fmaf(qv, kv1, acc[1][1]);
                    qv = qr[2*SX + d]; acc[2][0] = fmaf(qv, kv0, acc[2][0]); acc[2][1] = fmaf(qv, kv1, acc[2][1]);
                    qv = qr[3*SX + d]; acc[3][0] = fmaf(qv, kv0, acc[3][0]); acc[3][1] = fmaf(qv, kv1, acc[3][1]);
                }
#pragma unroll
                for (int i = 0; i < 4; ++i) {
                    s_sc[(nl0+i)*SS + m0]     = fmaxf(acc[i][0], 0.0f);
                    s_sc[(nl0+i)*SS + m0 + 1] = fmaxf(acc[i][1], 0.0f);
                }
            }
            __syncthreads();

            // ---------- P7: row softmax -> local supports ----------
            {
                const int w    = tid >> 5;   // local row 0..15
                const int lane = tid & 31;
                const float v0 = s_sc[w*SS + lane];
                const float v1 = s_sc[w*SS + 32 + lane];
                float mx = fmaxf(v0, v1);
#pragma unroll
                for (int o = 16; o > 0; o >>= 1) mx = fmaxf(mx, __shfl_xor_sync(0xffffffffu, mx, o));
                const float e0 = __expf(v0 - mx);
                const float e1 = __expf(v1 - mx);
                float s = e0 + e1;
#pragma unroll
                for (int o = 16; o > 0; o >>= 1) s += __shfl_xor_sync(0xffffffffu, s, o);
                const float inv = 1.0f / s;
                s_sup[w*SS + lane]      = e0 * inv;
                s_sup[w*SS + 32 + lane] = e1 * inv;
            }
            __syncthreads();
        }

        // Store h_last quarter into output_hidden
        for (int i = tid; i < RP * HH; i += NTH) {
            const int lr = i >> 7, c = i & 127;
            out[((size_t)layer * BB + batch) * NN * HH + (size_t)(R0 + lr) * HH + c]
                = s_h[(R0 + lr) * SX + c];
        }
        __syncthreads();
    }
}

extern "C" void kernel_launch(void* const* d_in, const int* in_sizes, int n_in,
                              void* d_out, int out_size) {
    (void)in_sizes; (void)n_in; (void)out_size;
    const float* inputs = (const float*)d_in[0];
    const float* h0     = (const float*)d_in[1];
    const float* sup    = (const float*)d_in[2];
    const float* Wg0    = (const float*)d_in[3];
    const float* bg0    = (const float*)d_in[4];
    const float* Wc0    = (const float*)d_in[5];
    const float* bc0    = (const float*)d_in[6];
    const float* Wq0    = (const float*)d_in[7];
    const float* Wk0    = (const float*)d_in[8];
    const float* Wg1    = (const float*)d_in[9];
    const float* bg1    = (const float*)d_in[10];
    const float* Wc1    = (const float*)d_in[11];
    const float* bc1    = (const float*)d_in[12];
    const float* Wq1    = (const float*)d_in[13];
    const float* Wk1    = (const float*)d_in[14];
    float* out          = (float*)d_out;

    static bool attr_set = false;
    if (!attr_set) {
        cudaFuncSetAttribute(sglc_kernel, cudaFuncAttributeMaxDynamicSharedMemorySize, SMEM_BYTES);
        attr_set = true;
    }

    sglc_kernel<<<BB * CLS, NTH, SMEM_BYTES>>>(inputs, h0, sup,
                                               Wg0, bg0, Wc0, bc0, Wq0, Wk0,
                                               Wg1, bg1, Wc1, bc1, Wq1, Wk1,
                                               out);
}

// round 16
// speedup vs baseline: 1.0079x; 1.0024x over previous
#include <cuda_runtime.h>
#include <math.h>
#include <stdint.h>

// Problem constants
#define TT 64
#define BB 32
#define NN 64
#define DD 128
#define HH 128

// Padded smem strides (floats)
#define SX 132   // 128-wide arrays (x, h, rh, u, q)
#define SC 260   // 256-wide (conv)
#define SS 68    // 64-wide (supports, scores)
#define SK 129   // k-vectors (conflict-free phase-6 reads)

#define CLS 4           // cluster size (CTAs per batch)
#define RP  16          // node rows per CTA
#define NTH 512

// Layer-0 hidden sequence scratch: (T, B, N*H) fp32 = 64 MB
__device__ float g_hs0[(size_t)TT * BB * NN * HH];

__device__ __forceinline__ float fsig(float x) { return 1.0f / (1.0f + __expf(-x)); }
__device__ __forceinline__ float ftanh_(float x) { return 1.0f - 2.0f / (__expf(2.0f * x) + 1.0f); }

__device__ __forceinline__ uint32_t smem_u32p(const void* p) {
    uint32_t a;
    asm("{ .reg .u64 t; cvta.to.shared.u64 t, %1; cvt.u32.u64 %0, t; }" : "=r"(a) : "l"(p));
    return a;
}
__device__ __forceinline__ uint32_t mapa_u32(uint32_t a, int r) {
    uint32_t d;
    asm("mapa.shared::cluster.u32 %0, %1, %2;" : "=r"(d) : "r"(a), "r"(r));
    return d;
}
__device__ __forceinline__ void st_cl_v2(uint32_t a, float x, float y) {
    asm volatile("st.shared::cluster.v2.f32 [%0], {%1, %2};" :: "r"(a), "f"(x), "f"(y) : "memory");
}
__device__ __forceinline__ void st_cl_f32(uint32_t a, float x) {
    asm volatile("st.shared::cluster.f32 [%0], %1;" :: "r"(a), "f"(x) : "memory");
}
#define CLUSTER_SYNC() do { \
    asm volatile("barrier.cluster.arrive.aligned;" ::: "memory"); \
    asm volatile("barrier.cluster.wait.aligned;" ::: "memory"); } while (0)

// K=128 segment, 4 rows x 2 cols accumulator
__device__ __forceinline__ void seg4(float acc[4][2],
    const float* __restrict__ r0, const float* __restrict__ r1,
    const float* __restrict__ r2, const float* __restrict__ r3,
    const float* __restrict__ W, int ldw)
{
#pragma unroll 4
    for (int k = 0; k < 128; ++k) {
        const float2 w = *(const float2*)(W + (size_t)k * ldw);
        float a;
        a = r0[k]; acc[0][0] = fmaf(a, w.x, acc[0][0]); acc[0][1] = fmaf(a, w.y, acc[0][1]);
        a = r1[k]; acc[1][0] = fmaf(a, w.x, acc[1][0]); acc[1][1] = fmaf(a, w.y, acc[1][1]);
        a = r2[k]; acc[2][0] = fmaf(a, w.x, acc[2][0]); acc[2][1] = fmaf(a, w.y, acc[2][1]);
        a = r3[k]; acc[3][0] = fmaf(a, w.x, acc[3][0]); acc[3][1] = fmaf(a, w.y, acc[3][1]);
    }
}

// K=128 segment, 2 rows x 2 cols accumulator
__device__ __forceinline__ void seg2(float acc[2][2],
    const float* __restrict__ r0, const float* __restrict__ r1,
    const float* __restrict__ W, int ldw)
{
#pragma unroll 4
    for (int k = 0; k < 128; ++k) {
        const float2 w = *(const float2*)(W + (size_t)k * ldw);
        float a;
        a = r0[k]; acc[0][0] = fmaf(a, w.x, acc[0][0]); acc[0][1] = fmaf(a, w.y, acc[0][1]);
        a = r1[k]; acc[1][0] = fmaf(a, w.x, acc[1][0]); acc[1][1] = fmaf(a, w.y, acc[1][1]);
    }
}

// conv rows [R0, R0+16) x 256 cols: conv[n,:] = sum_m sup_local[n,m] * [srcx | srch][m,:]
// 256 threads: 4 row-groups (4 rows) x 64 float4-col-groups
__device__ __forceinline__ void conv_phase(int tid,
    const float* __restrict__ srcx, const float* __restrict__ srch,
    const float* __restrict__ s_sup, float* __restrict__ s_conv)
{
    const int rowg = tid >> 6;          // 0..3
    const int nl0  = rowg << 2;         // local rows nl0..nl0+3
    const int c4   = (tid & 63) << 2;   // 0..252
    const float* src = (c4 < 128) ? (srcx + c4) : (srch + (c4 - 128));
    const float* sup = s_sup + nl0 * SS;
    float4 a0 = make_float4(0.f,0.f,0.f,0.f), a1 = a0, a2 = a0, a3 = a0;
#pragma unroll 4
    for (int m = 0; m < NN; ++m) {
        const float4 v = *(const float4*)(src + m * SX);
        const float sA = sup[m], sB = sup[SS + m], sC = sup[2*SS + m], sD = sup[3*SS + m];
        a0.x = fmaf(sA, v.x, a0.x); a0.y = fmaf(sA, v.y, a0.y); a0.z = fmaf(sA, v.z, a0.z); a0.w = fmaf(sA, v.w, a0.w);
        a1.x = fmaf(sB, v.x, a1.x); a1.y = fmaf(sB, v.y, a1.y); a1.z = fmaf(sB, v.z, a1.z); a1.w = fmaf(sB, v.w, a1.w);
        a2.x = fmaf(sC, v.x, a2.x); a2.y = fmaf(sC, v.y, a2.y); a2.z = fmaf(sC, v.z, a2.z); a2.w = fmaf(sC, v.w, a2.w);
        a3.x = fmaf(sD, v.x, a3.x); a3.y = fmaf(sD, v.y, a3.y); a3.z = fmaf(sD, v.z, a3.z); a3.w = fmaf(sD, v.w, a3.w);
    }
    *(float4*)(s_conv + (nl0+0) * SC + c4) = a0;
    *(float4*)(s_conv + (nl0+1) * SC + c4) = a1;
    *(float4*)(s_conv + (nl0+2) * SC + c4) = a2;
    *(float4*)(s_conv + (nl0+3) * SC + c4) = a3;
}

// smem floats: 3*64*SX + 64*SK + 2*16*SX + 16*SC + 16*SS
#define SMEM_FLOATS (3*64*SX + 64*SK + 2*16*SX + 16*SC + 16*SS)
#define SMEM_BYTES  (SMEM_FLOATS * (int)sizeof(float))

__global__ void __launch_bounds__(NTH, 1) __cluster_dims__(CLS, 1, 1)
sglc_kernel(const float* __restrict__ inputs,
            const float* __restrict__ h0_all,
            const float* __restrict__ sup0,
            const float* __restrict__ Wg0, const float* __restrict__ bg0,
            const float* __restrict__ Wc0, const float* __restrict__ bc0,
            const float* __restrict__ Wq0, const float* __restrict__ Wk0,
            const float* __restrict__ Wg1, const float* __restrict__ bg1,
            const float* __restrict__ Wc1, const float* __restrict__ bc1,
            const float* __restrict__ Wq1, const float* __restrict__ Wk1,
            float* __restrict__ out)
{
    extern __shared__ float sm[];
    float* s_x    = sm;                    // 64 x SX (full)
    float* s_h    = s_x  + 64 * SX;        // 64 x SX (full, replicated)
    float* s_rh   = s_h  + 64 * SX;        // 64 x SX (full, replicated)
    float* s_k    = s_rh + 64 * SX;        // 64 x SK (full, replicated)
    float* s_q    = s_k  + 64 * SK;        // 16 x SX (local quarter)
    float* s_u    = s_q  + 16 * SX;        // 16 x SX (local quarter)
    float* s_conv = s_u  + 16 * SX;        // 16 x SC (local quarter)
    float* s_sup  = s_conv + 16 * SC;      // 16 x SS (local quarter)
    float* s_sc   = s_u;                   // scores alias (16 x SS fits)

    const int tid   = threadIdx.x;
    const int batch = blockIdx.x >> 2;
    const int rank  = blockIdx.x & 3;
    const int R0    = rank * RP;

    // Peer smem base addresses (all 4 ranks) for push-broadcast buffers
    const uint32_t rh_u = smem_u32p(s_rh);
    const uint32_t h_u  = smem_u32p(s_h);
    const uint32_t k_u  = smem_u32p(s_k);
    uint32_t rh_p[CLS], h_p[CLS], k_p[CLS];
#pragma unroll
    for (int r = 0; r < CLS; ++r) {
        rh_p[r] = mapa_u32(rh_u, r);
        h_p[r]  = mapa_u32(h_u, r);
        k_p[r]  = mapa_u32(k_u, r);
    }

    // Load local 16 rows of initial supports
    for (int i = tid; i < RP * NN; i += NTH) {
        const int lr = i >> 6, c = i & 63;
        s_sup[lr * SS + c] = sup0[(size_t)batch * NN * NN + (R0 + lr) * NN + c];
    }

    for (int layer = 0; layer < 2; ++layer) {
        const float* Wg = layer ? Wg1 : Wg0;
        const float* bg = layer ? bg1 : bg0;
        const float* Wc = layer ? Wc1 : Wc0;
        const float* bc = layer ? bc1 : bc0;
        const float* Wq = layer ? Wq1 : Wq0;
        const float* Wk = layer ? Wk1 : Wk0;

        // Full initial hidden state (each CTA holds a replica)
        for (int i = tid; i < NN * HH; i += NTH)
            s_h[(i >> 7) * SX + (i & 127)] = h0_all[((size_t)layer * BB + batch) * NN * HH + i];
        __syncthreads();

        for (int t = 0; t < TT; ++t) {
            // ---------- P0: load full x_t ----------
            const float* xsrc = (layer == 0)
                ? inputs + (size_t)(t * BB + batch) * NN * DD
                : g_hs0  + (size_t)(t * BB + batch) * NN * HH;
            for (int i = tid; i < NN * 32; i += NTH) {
                const int row = i >> 5, c4 = (i & 31) << 2;
                *(float4*)(s_x + row * SX + c4) = *(const float4*)(xsrc + row * 128 + c4);
            }
            __syncthreads();

            // ---------- P1: conv = sup_local @ [x|h] (16 rows) ----------
            if (tid < 256) conv_phase(tid, s_x, s_h, s_sup, s_conv);
            __syncthreads();

            // ---------- P2: gates (16 rows x 256 cols, K=512) ----------
            {
                const int rowg = tid >> 7;          // 0..3
                const int nl0  = rowg << 2;
                const int j0   = (tid & 127) << 1;  // 0..254
                const int gn0  = R0 + nl0;
                float acc[4][2];
                const float b0v = bg[j0], b1v = bg[j0 + 1];
#pragma unroll
                for (int i = 0; i < 4; ++i) { acc[i][0] = b0v; acc[i][1] = b1v; }
                seg4(acc, s_x + (gn0+0)*SX, s_x + (gn0+1)*SX, s_x + (gn0+2)*SX, s_x + (gn0+3)*SX,
                     Wg + j0, 256);
                seg4(acc, s_h + (gn0+0)*SX, s_h + (gn0+1)*SX, s_h + (gn0+2)*SX, s_h + (gn0+3)*SX,
                     Wg + 128*256 + j0, 256);
                seg4(acc, s_conv + (nl0+0)*SC, s_conv + (nl0+1)*SC, s_conv + (nl0+2)*SC, s_conv + (nl0+3)*SC,
                     Wg + 256*256 + j0, 256);
                seg4(acc, s_conv + (nl0+0)*SC + 128, s_conv + (nl0+1)*SC + 128,
                     s_conv + (nl0+2)*SC + 128, s_conv + (nl0+3)*SC + 128,
                     Wg + 384*256 + j0, 256);
                if (j0 < 128) {
#pragma unroll
                    for (int i = 0; i < 4; ++i) {
                        const int gn = gn0 + i;
                        const float rv0 = fsig(acc[i][0]) * s_h[gn*SX + j0];
                        const float rv1 = fsig(acc[i][1]) * s_h[gn*SX + j0 + 1];
                        s_rh[gn*SX + j0]     = rv0;
                        s_rh[gn*SX + j0 + 1] = rv1;
                        const uint32_t off = (uint32_t)(gn * SX + j0) * 4u;
#pragma unroll
                        for (int rr = 0; rr < CLS; ++rr)
                            if (rr != rank) st_cl_v2(rh_p[rr] + off, rv0, rv1);
                    }
                } else {
                    const int ju = j0 - 128;
#pragma unroll
                    for (int i = 0; i < 4; ++i) {
                        s_u[(nl0+i)*SX + ju]     = fsig(acc[i][0]);
                        s_u[(nl0+i)*SX + ju + 1] = fsig(acc[i][1]);
                    }
                }
            }
            CLUSTER_SYNC();   // B1: rh replicas complete everywhere

            // ---------- P3: conv_c = sup_local @ [x|rh] ----------
            if (tid < 256) conv_phase(tid, s_x, s_rh, s_sup, s_conv);
            __syncthreads();

            // ---------- P4: c = tanh(...), h = u*h + (1-u)*c ----------
            float* hdst = (layer == 0)
                ? g_hs0 + (size_t)(t * BB + batch) * NN * HH
                : out + (size_t)2 * BB * NN * HH + (size_t)(t * BB + batch) * NN * HH;
            {
                const int rowg = tid >> 6;          // 0..7
                const int nl0  = rowg << 1;
                const int j0   = (tid & 63) << 1;   // 0..126
                const int gn0  = R0 + nl0;
                float acc[2][2];
                const float b0v = bc[j0], b1v = bc[j0 + 1];
                acc[0][0] = b0v; acc[0][1] = b1v; acc[1][0] = b0v; acc[1][1] = b1v;
                seg2(acc, s_x  + (gn0+0)*SX, s_x  + (gn0+1)*SX, Wc + j0, 128);
                seg2(acc, s_rh + (gn0+0)*SX, s_rh + (gn0+1)*SX, Wc + 128*128 + j0, 128);
                seg2(acc, s_conv + (nl0+0)*SC, s_conv + (nl0+1)*SC, Wc + 256*128 + j0, 128);
                seg2(acc, s_conv + (nl0+0)*SC + 128, s_conv + (nl0+1)*SC + 128, Wc + 384*128 + j0, 128);
#pragma unroll
                for (int i = 0; i < 2; ++i) {
                    const int gn = gn0 + i, nl = nl0 + i;
                    const float c0 = ftanh_(acc[i][0]);
                    const float c1 = ftanh_(acc[i][1]);
                    const float u0 = s_u[nl*SX + j0], u1 = s_u[nl*SX + j0 + 1];
                    const float hn0 = u0 * s_h[gn*SX + j0]     + (1.0f - u0) * c0;
                    const float hn1 = u1 * s_h[gn*SX + j0 + 1] + (1.0f - u1) * c1;
                    s_h[gn*SX + j0]     = hn0;
                    s_h[gn*SX + j0 + 1] = hn1;
                    const uint32_t off = (uint32_t)(gn * SX + j0) * 4u;
#pragma unroll
                    for (int rr = 0; rr < CLS; ++rr)
                        if (rr != rank) st_cl_v2(h_p[rr] + off, hn0, hn1);
                    *(float2*)(hdst + gn * HH + j0) = make_float2(hn0, hn1);
                }
            }
            __syncthreads();

            // ---------- P5: q (local) | k (replicated) = h_new @ [Wq|Wk] ----------
            {
                const int rowg = tid >> 7;
                const int nl0  = rowg << 2;
                const int j0   = (tid & 127) << 1;
                const int gn0  = R0 + nl0;
                float acc[4][2];
#pragma unroll
                for (int i = 0; i < 4; ++i) { acc[i][0] = 0.f; acc[i][1] = 0.f; }
                const float* Wb = (j0 < 128) ? (Wq + j0) : (Wk + (j0 - 128));
                seg4(acc, s_h + (gn0+0)*SX, s_h + (gn0+1)*SX, s_h + (gn0+2)*SX, s_h + (gn0+3)*SX,
                     Wb, 128);
                if (j0 < 128) {
#pragma unroll
                    for (int i = 0; i < 4; ++i) {
                        s_q[(nl0+i)*SX + j0]     = acc[i][0];
                        s_q[(nl0+i)*SX + j0 + 1] = acc[i][1];
                    }
                } else {
                    const int jk = j0 - 128;
#pragma unroll
                    for (int i = 0; i < 4; ++i) {
                        const int gn = gn0 + i;
                        s_k[gn*SK + jk]     = acc[i][0];
                        s_k[gn*SK + jk + 1] = acc[i][1];
                        const uint32_t off = (uint32_t)(gn * SK + jk) * 4u;
#pragma unroll
                        for (int rr = 0; rr < CLS; ++rr)
                            if (rr != rank) {
                                st_cl_f32(k_p[rr] + off,     acc[i][0]);
                                st_cl_f32(k_p[rr] + off + 4, acc[i][1]);
                            }
                    }
                }
            }
            CLUSTER_SYNC();   // B2: h and k replicas complete everywhere

            // ---------- P6: scores = relu(q_local @ k_full^T) (16 x 64) ----------
            if (tid < 128) {
                const int rowg = tid >> 5;      // 0..3
                const int nl0  = rowg << 2;     // 4 local rows
                const int lane = tid & 31;
                const int m0   = lane << 1;
                float acc[4][2];
#pragma unroll
                for (int i = 0; i < 4; ++i) { acc[i][0] = 0.f; acc[i][1] = 0.f; }
                const float* qr = s_q + nl0 * SX;
                const float* k0p = s_k + m0 * SK;
                const float* k1p = k0p + SK;
#pragma unroll 4
                for (int d = 0; d < 128; ++d) {
                    const float kv0 = k0p[d], kv1 = k1p[d];
                    float qv;
                    qv = qr[d];        acc[0][0] = fmaf(qv, kv0, acc[0][0]); acc[0][1] = fmaf(qv, kv1, acc[0][1]);
                    qv = qr[SX + d];   acc[1][0] = fmaf(qv, kv0, acc[1][0]); acc[1][1] = fmaf(qv, kv1, acc[1][1]);
                    qv = qr[2*SX + d]; acc[2][0] = fmaf(qv, kv0, acc[2][0]); acc[2][1] = fmaf(qv, kv1, acc[2][1]);
                    qv = qr[3*SX + d]; acc[3][0] = fmaf(qv, kv0, acc[3][0]); acc[3][1] = fmaf(qv, kv1, acc[3][1]);
                }
#pragma unroll
                for (int i = 0; i < 4; ++i) {
                    s_sc[(nl0+i)*SS + m0]     = fmaxf(acc[i][0], 0.0f);
                    s_sc[(nl0+i)*SS + m0 + 1] = fmaxf(acc[i][1], 0.0f);
                }
            }
            __syncthreads();

            // ---------- P7: row softmax -> local supports ----------
            {
                const int w    = tid >> 5;   // local row 0..15
                const int lane = tid & 31;
                const float v0 = s_sc[w*SS + lane];
                const float v1 = s_sc[w*SS + 32 + lane];
                float mx = fmaxf(v0, v1);
#pragma unroll
                for (int o = 16; o > 0; o >>= 1) mx = fmaxf(mx, __shfl_xor_sync(0xffffffffu, mx, o));
                const float e0 = __expf(v0 - mx);
                const float e1 = __expf(v1 - mx);
                float s = e0 + e1;
#pragma unroll
                for (int o = 16; o > 0; o >>= 1) s += __shfl_xor_sync(0xffffffffu, s, o);
                const float inv = 1.0f / s;
                s_sup[w*SS + lane]      = e0 * inv;
                s_sup[w*SS + 32 + lane] = e1 * inv;
            }
            __syncthreads();
        }

        // Store h_last quarter into output_hidden
        for (int i = tid; i < RP * HH; i += NTH) {
            const int lr = i >> 7, c = i & 127;
            out[((size_t)layer * BB + batch) * NN * HH + (size_t)(R0 + lr) * HH + c]
                = s_h[(R0 + lr) * SX + c];
        }
        __syncthreads();
    }
}

extern "C" void kernel_launch(void* const* d_in, const int* in_sizes, int n_in,
                              void* d_out, int out_size) {
    (void)in_sizes; (void)n_in; (void)out_size;
    const float* inputs = (const float*)d_in[0];
    const float* h0     = (const float*)d_in[1];
    const float* sup    = (const float*)d_in[2];
    const float* Wg0    = (const float*)d_in[3];
    const float* bg0    = (const float*)d_in[4];
    const float* Wc0    = (const float*)d_in[5];
    const float* bc0    = (const float*)d_in[6];
    const float* Wq0    = (const float*)d_in[7];
    const float* Wk0    = (const float*)d_in[8];
    const float* Wg1    = (const float*)d_in[9];
    const float* bg1    = (const float*)d_in[10];
    const float* Wc1    = (const float*)d_in[11];
    const float* bc1    = (const float*)d_in[12];
    const float* Wq1    = (const float*)d_in[13];
    const float* Wk1    = (const float*)d_in[14];
    float* out          = (float*)d_out;

    static bool attr_set = false;
    if (!attr_set) {
        cudaFuncSetAttribute(sglc_kernel, cudaFuncAttributeMaxDynamicSharedMemorySize, SMEM_BYTES);
        attr_set = true;
    }

    sglc_kernel<<<BB * CLS, NTH, SMEM_BYTES>>>(inputs, h0, sup,
                                               Wg0, bg0, Wc0, bc0, Wq0, Wk0,
                                               Wg1, bg1, Wc1, bc1, Wq1, Wk1,
                                               out);
}